// round 2
// baseline (speedup 1.0000x reference)
#include <cuda_runtime.h>
#include <math.h>

#define LSEQ   2048
#define CDIM   512
#define HID    512
#define OQKV   1536
#define BATCH  4
#define NHEADS 8
#define DHEAD  64

// Scratch (allocation-free rule: __device__ globals)
__device__ float g_qkv[(size_t)BATCH * OQKV * LSEQ];   // [b, 1536, 2048]
__device__ float g_attn[(size_t)BATCH * HID * LSEQ];   // [b,  512, 2048]

// ---------------------------------------------------------------------------
// Batched SGEMM: C[b] = A @ B[b] (+ bias)
// A: [M,K] row-major (shared across batch), B: [K,N] row-major, C: [M,N]
// ---------------------------------------------------------------------------
#define BM 64
#define BN 64
#define BK 16

__global__ __launch_bounds__(256) void gemm_kernel(
    const float* __restrict__ A, const float* __restrict__ Bg,
    float* __restrict__ Cg, int M, int N, int K,
    const float* __restrict__ bias)
{
    __shared__ float As[BK][BM];
    __shared__ float Bs[BK][BN];

    const float* B = Bg + (size_t)blockIdx.z * K * N;
    float*       C = Cg + (size_t)blockIdx.z * M * N;

    const int m0 = blockIdx.y * BM;
    const int n0 = blockIdx.x * BN;
    const int tid = threadIdx.x;
    const int tx = tid & 15, ty = tid >> 4;

    // load index maps
    const int arow = tid >> 2;          // 0..63
    const int acol = (tid & 3) * 4;     // 0,4,8,12
    const int brow = tid >> 4;          // 0..15
    const int bcol = (tid & 15) * 4;    // 0..60

    float acc[4][4] = {};

    for (int k0 = 0; k0 < K; k0 += BK) {
        float4 a4 = *(const float4*)&A[(size_t)(m0 + arow) * K + k0 + acol];
        As[acol + 0][arow] = a4.x;
        As[acol + 1][arow] = a4.y;
        As[acol + 2][arow] = a4.z;
        As[acol + 3][arow] = a4.w;
        *(float4*)&Bs[brow][bcol] =
            *(const float4*)&B[(size_t)(k0 + brow) * N + n0 + bcol];
        __syncthreads();

        #pragma unroll
        for (int k = 0; k < BK; k++) {
            float4 av = *(const float4*)&As[k][ty * 4];
            float4 bv = *(const float4*)&Bs[k][tx * 4];
            float ar[4] = {av.x, av.y, av.z, av.w};
            float br[4] = {bv.x, bv.y, bv.z, bv.w};
            #pragma unroll
            for (int r = 0; r < 4; r++)
                #pragma unroll
                for (int c = 0; c < 4; c++)
                    acc[r][c] += ar[r] * br[c];
        }
        __syncthreads();
    }

    #pragma unroll
    for (int r = 0; r < 4; r++) {
        float bb = bias ? bias[m0 + ty * 4 + r] : 0.0f;
        float4 o4 = make_float4(acc[r][0] + bb, acc[r][1] + bb,
                                acc[r][2] + bb, acc[r][3] + bb);
        *(float4*)&C[(size_t)(m0 + ty * 4 + r) * N + n0 + tx * 4] = o4;
    }
}

// ---------------------------------------------------------------------------
// Flash attention, fp32. One block = (b, h, 64-query tile). 256 threads.
// qkv layout: [b, o, l] with q at o=h*64+d, k at o=512+h*64+d, v at o=1024+...
// Output: attn_out[b, h*64+d, i] = O[i, d]
// ---------------------------------------------------------------------------
__global__ __launch_bounds__(256) void attn_kernel(
    const float* __restrict__ qkv, float* __restrict__ attn_out)
{
    extern __shared__ float sm[];
    float* Qs = sm;                 // [64][64]  (d, ii)
    float* Ks = Qs + 64 * 64;       // [64][64]  (d, jj)
    float* Vs = Ks + 64 * 64;       // [64][64]  (jj, d)   -- transposed
    float* Ps = Vs + 64 * 64;       // [64][64]  (ii, jj) / reused as (d, ii)

    const int i0 = blockIdx.x * 64;
    const int h  = blockIdx.y;
    const int b  = blockIdx.z;

    const float* qb = qkv + ((size_t)b * OQKV + h * DHEAD) * LSEQ;
    const float* kb = qb + (size_t)HID * LSEQ;
    const float* vb = kb + (size_t)HID * LSEQ;

    const int tid = threadIdx.x;
    const int tx = tid & 15, ty = tid >> 4;
    const int ld_d = tid >> 2;           // 0..63
    const int ld_s = (tid & 3) * 16;     // 0,16,32,48

    const float SCALE = 0.125f;          // 64^-0.5

    // Load Q tile (pre-scaled)
    #pragma unroll
    for (int xx = 0; xx < 4; xx++) {
        float4 v4 = *(const float4*)&qb[(size_t)ld_d * LSEQ + i0 + ld_s + xx * 4];
        v4.x *= SCALE; v4.y *= SCALE; v4.z *= SCALE; v4.w *= SCALE;
        *(float4*)&Qs[ld_d * 64 + ld_s + xx * 4] = v4;
    }

    float m_r[4], l_r[4], o_acc[4][4] = {};
    #pragma unroll
    for (int r = 0; r < 4; r++) { m_r[r] = -1e30f; l_r[r] = 0.0f; }

    for (int j0 = 0; j0 < LSEQ; j0 += 64) {
        // Load K (d, jj) and V transposed (jj, d)
        #pragma unroll
        for (int xx = 0; xx < 4; xx++) {
            *(float4*)&Ks[ld_d * 64 + ld_s + xx * 4] =
                *(const float4*)&kb[(size_t)ld_d * LSEQ + j0 + ld_s + xx * 4];
            float4 vv = *(const float4*)&vb[(size_t)ld_d * LSEQ + j0 + ld_s + xx * 4];
            Vs[(ld_s + xx * 4 + 0) * 64 + ld_d] = vv.x;
            Vs[(ld_s + xx * 4 + 1) * 64 + ld_d] = vv.y;
            Vs[(ld_s + xx * 4 + 2) * 64 + ld_d] = vv.z;
            Vs[(ld_s + xx * 4 + 3) * 64 + ld_d] = vv.w;
        }
        __syncthreads();

        // S = Q^T K  (4x4 per thread: rows ty*4+r, cols tx*4+c)
        float s[4][4] = {};
        #pragma unroll 16
        for (int d = 0; d < 64; d++) {
            float4 qa = *(const float4*)&Qs[d * 64 + ty * 4];
            float4 kk = *(const float4*)&Ks[d * 64 + tx * 4];
            float ar[4] = {qa.x, qa.y, qa.z, qa.w};
            float br[4] = {kk.x, kk.y, kk.z, kk.w};
            #pragma unroll
            for (int r = 0; r < 4; r++)
                #pragma unroll
                for (int c = 0; c < 4; c++)
                    s[r][c] += ar[r] * br[c];
        }

        // Online softmax per row (16-lane groups along tx)
        #pragma unroll
        for (int r = 0; r < 4; r++) {
            float mx = fmaxf(fmaxf(s[r][0], s[r][1]), fmaxf(s[r][2], s[r][3]));
            #pragma unroll
            for (int off = 8; off > 0; off >>= 1)
                mx = fmaxf(mx, __shfl_xor_sync(0xffffffffu, mx, off));
            float mnew = fmaxf(m_r[r], mx);
            float resc = __expf(m_r[r] - mnew);
            float sum = 0.0f;
            #pragma unroll
            for (int c = 0; c < 4; c++) {
                s[r][c] = __expf(s[r][c] - mnew);
                sum += s[r][c];
            }
            #pragma unroll
            for (int off = 8; off > 0; off >>= 1)
                sum += __shfl_xor_sync(0xffffffffu, sum, off);
            l_r[r] = l_r[r] * resc + sum;
            m_r[r] = mnew;
            #pragma unroll
            for (int c = 0; c < 4; c++)
                o_acc[r][c] *= resc;
            float4 pv = make_float4(s[r][0], s[r][1], s[r][2], s[r][3]);
            *(float4*)&Ps[(ty * 4 + r) * 64 + tx * 4] = pv;
        }
        __syncthreads();

        // O += P @ V^T  (o[r][c]: row ii=ty*4+r, col d=tx*4+c)
        #pragma unroll 8
        for (int jj = 0; jj < 64; jj++) {
            float pr[4];
            #pragma unroll
            for (int r = 0; r < 4; r++)
                pr[r] = Ps[(ty * 4 + r) * 64 + jj];
            float4 vv = *(const float4*)&Vs[jj * 64 + tx * 4];
            float vr[4] = {vv.x, vv.y, vv.z, vv.w};
            #pragma unroll
            for (int r = 0; r < 4; r++)
                #pragma unroll
                for (int c = 0; c < 4; c++)
                    o_acc[r][c] += pr[r] * vr[c];
        }
        __syncthreads();
    }

    // Normalize + transpose via smem (Ps reused as (d, ii)), coalesced write
    #pragma unroll
    for (int r = 0; r < 4; r++) {
        float inv = 1.0f / l_r[r];
        #pragma unroll
        for (int c = 0; c < 4; c++)
            Ps[(tx * 4 + c) * 64 + ty * 4 + r] = o_acc[r][c] * inv;
    }
    __syncthreads();

    float* ob = attn_out + ((size_t)b * HID + h * DHEAD) * LSEQ;
    #pragma unroll
    for (int xx = 0; xx < 4; xx++) {
        *(float4*)&ob[(size_t)ld_d * LSEQ + i0 + ld_s + xx * 4] =
            *(float4*)&Ps[ld_d * 64 + ld_s + xx * 4];
    }
}

// ---------------------------------------------------------------------------
extern "C" void kernel_launch(void* const* d_in, const int* in_sizes, int n_in,
                              void* d_out, int out_size)
{
    const float* x      = (const float*)d_in[0];   // [4, 512, 2048]
    const float* w_qkv  = (const float*)d_in[1];   // [1536, 512]
    const float* w_out  = (const float*)d_in[2];   // [512, 512]
    const float* b_out  = (const float*)d_in[3];   // [512]
    float*       out    = (float*)d_out;           // [4, 512, 2048]

    float *qkv_ptr, *attn_ptr;
    cudaGetSymbolAddress((void**)&qkv_ptr, g_qkv);
    cudaGetSymbolAddress((void**)&attn_ptr, g_attn);

    // 1) QKV projection: [1536,512] x [b,512,2048] -> g_qkv
    {
        dim3 grid(LSEQ / BN, OQKV / BM, BATCH);
        gemm_kernel<<<grid, 256>>>(w_qkv, x, qkv_ptr, OQKV, LSEQ, CDIM, nullptr);
    }

    // 2) Flash attention -> g_attn  [b, (h d), l]
    {
        static int smem_set = 0;
        (void)smem_set;
        cudaFuncSetAttribute(attn_kernel,
                             cudaFuncAttributeMaxDynamicSharedMemorySize,
                             4 * 64 * 64 * (int)sizeof(float));
        dim3 grid(LSEQ / 64, NHEADS, BATCH);
        attn_kernel<<<grid, 256, 4 * 64 * 64 * sizeof(float)>>>(qkv_ptr, attn_ptr);
    }

    // 3) Out projection + bias: [512,512] x [b,512,2048] -> out
    {
        dim3 grid(LSEQ / BN, HID / BM, BATCH);
        gemm_kernel<<<grid, 256>>>(w_out, attn_ptr, out, HID, LSEQ, HID, b_out);
    }
}

// round 3
// speedup vs baseline: 3.1523x; 3.1523x over previous
#include <cuda_runtime.h>

#define LSEQ   2048
#define CDIM   512
#define HID    512
#define OQKV   1536
#define BATCH  4
#define NHEADS 8
#define DHEAD  64

__device__ float g_qkv[(size_t)BATCH * OQKV * LSEQ];
__device__ float g_attn[(size_t)BATCH * HID * LSEQ];

__device__ __forceinline__ unsigned f2tf(float x) {
    unsigned u; asm("cvt.rna.tf32.f32 %0, %1;" : "=r"(u) : "f"(x)); return u;
}
__device__ __forceinline__ float fast_ex2(float x) {
    float y; asm("ex2.approx.ftz.f32 %0, %1;" : "=f"(y) : "f"(x)); return y;
}
// D += A*B, m16n8k8 tf32
__device__ __forceinline__ void mma8(float* c, const unsigned* a, const unsigned* b) {
    asm volatile(
        "mma.sync.aligned.m16n8k8.row.col.f32.tf32.tf32.f32 "
        "{%0,%1,%2,%3}, {%4,%5,%6,%7}, {%8,%9}, {%0,%1,%2,%3};"
        : "+f"(c[0]), "+f"(c[1]), "+f"(c[2]), "+f"(c[3])
        : "r"(a[0]), "r"(a[1]), "r"(a[2]), "r"(a[3]), "r"(b[0]), "r"(b[1]));
}

// ---------------------------------------------------------------------------
// Tensor-core GEMM: C[b] = A @ B[b] (+bias). A:[M,K], B:[K,N], C:[M,N] row-maj
// Block tile 128x128, BK=16, 8 warps, warp tile 32x64.
// Fragment-layout smem with XOR swizzle.
// ---------------------------------------------------------------------------
__global__ __launch_bounds__(256, 2) void gemm_tc(
    const float* __restrict__ A, const float* __restrict__ Bg,
    float* __restrict__ Cg, int M, int N, int K,
    const float* __restrict__ bias)
{
    __shared__ unsigned As[2 * 8 * 128];    // [k8][ma][lane*4+slot]
    __shared__ unsigned Bs[2 * 16 * 66];    // [k8][na][lane*2+slot], pad 66

    const float* B = Bg + (size_t)blockIdx.z * K * N;
    float*       C = Cg + (size_t)blockIdx.z * M * N;
    const int m0 = blockIdx.y * 128, n0 = blockIdx.x * 128;
    const int tid = threadIdx.x;
    const int warp = tid >> 5, lane = tid & 31;
    const int wm = warp >> 1, wn = warp & 1;
    const int g = lane >> 2, t = lane & 3;
    const int phys = lane ^ g;

    // loader maps
    const int arow = tid >> 1;          // 0..127
    const int akb  = (tid & 1) * 8;     // 0 or 8
    const int bkr  = warp;              // rows bkr, bkr+8
    const int bn4  = lane * 4;          // 0..124
    const int bna  = lane >> 1;
    const int bglo = 4 * (lane & 1);

    float acc[2][8][4];
    #pragma unroll
    for (int i = 0; i < 2; i++)
        #pragma unroll
        for (int j = 0; j < 8; j++)
            #pragma unroll
            for (int c = 0; c < 4; c++) acc[i][j][c] = 0.0f;

    // prefetch tile 0
    float4 ra[2], rb[2];
    ra[0] = *(const float4*)&A[(size_t)(m0 + arow) * K + akb];
    ra[1] = *(const float4*)&A[(size_t)(m0 + arow) * K + akb + 4];
    rb[0] = *(const float4*)&B[(size_t)bkr * N + n0 + bn4];
    rb[1] = *(const float4*)&B[(size_t)(bkr + 8) * N + n0 + bn4];

    for (int k0 = 0; k0 < K; k0 += 16) {
        __syncthreads();
        // ---- store A frag ----
        {
            const int k8 = akb >> 3;
            const int ma = arow >> 4, gA = arow & 7, mh = (arow >> 3) & 1;
            float av[8] = {ra[0].x, ra[0].y, ra[0].z, ra[0].w,
                           ra[1].x, ra[1].y, ra[1].z, ra[1].w};
            #pragma unroll
            for (int j = 0; j < 8; j++) {
                int tA = j & 3, kh = j >> 2;
                int ln = gA * 4 + tA, ph = ln ^ (ln >> 2);
                As[(k8 * 8 + ma) * 128 + ph * 4 + (mh + 2 * kh)] = f2tf(av[j]);
            }
        }
        // ---- store B frag ----
        #pragma unroll
        for (int q = 0; q < 2; q++) {
            const int kr = bkr + 8 * q;
            const int k8 = q, tB = kr & 3, slB = (kr >> 2) & 1;
            float bv[4] = {rb[q].x, rb[q].y, rb[q].z, rb[q].w};
            #pragma unroll
            for (int e = 0; e < 4; e++) {
                int gB = bglo + e;
                int ln = gB * 4 + tB, ph = ln ^ (ln >> 2);
                Bs[(k8 * 16 + bna) * 66 + ph * 2 + slB] = f2tf(bv[e]);
            }
        }
        __syncthreads();

        if (k0 + 16 < K) {
            ra[0] = *(const float4*)&A[(size_t)(m0 + arow) * K + k0 + 16 + akb];
            ra[1] = *(const float4*)&A[(size_t)(m0 + arow) * K + k0 + 16 + akb + 4];
            rb[0] = *(const float4*)&B[(size_t)(k0 + 16 + bkr) * N + n0 + bn4];
            rb[1] = *(const float4*)&B[(size_t)(k0 + 16 + bkr + 8) * N + n0 + bn4];
        }

        #pragma unroll
        for (int k8 = 0; k8 < 2; k8++) {
            unsigned af[2][4];
            #pragma unroll
            for (int i2 = 0; i2 < 2; i2++) {
                uint4 v = *(const uint4*)&As[(k8 * 8 + wm * 2 + i2) * 128 + phys * 4];
                af[i2][0] = v.x; af[i2][1] = v.y; af[i2][2] = v.z; af[i2][3] = v.w;
            }
            #pragma unroll
            for (int j8 = 0; j8 < 8; j8++) {
                uint2 bf = *(const uint2*)&Bs[(k8 * 16 + wn * 8 + j8) * 66 + phys * 2];
                unsigned bb[2] = {bf.x, bf.y};
                mma8(acc[0][j8], af[0], bb);
                mma8(acc[1][j8], af[1], bb);
            }
        }
    }

    // epilogue
    #pragma unroll
    for (int i2 = 0; i2 < 2; i2++) {
        int row = m0 + wm * 32 + i2 * 16 + g;
        float b0 = bias ? bias[row] : 0.0f;
        float b1 = bias ? bias[row + 8] : 0.0f;
        #pragma unroll
        for (int j8 = 0; j8 < 8; j8++) {
            int col = n0 + wn * 64 + j8 * 8 + 2 * t;
            float2 v0 = make_float2(acc[i2][j8][0] + b0, acc[i2][j8][1] + b0);
            float2 v1 = make_float2(acc[i2][j8][2] + b1, acc[i2][j8][3] + b1);
            *(float2*)&C[(size_t)row * N + col] = v0;
            *(float2*)&C[(size_t)(row + 8) * N + col] = v1;
        }
    }
}

// ---------------------------------------------------------------------------
// Flash attention, tf32 tensor cores. Block = (128 q-rows, h, b), 8 warps,
// each warp owns 16 query rows -> softmax is quad-shuffle local.
// ---------------------------------------------------------------------------
#define ATT_SMEM_WORDS (8448 + 4480 + 4480 + 8448)

__global__ __launch_bounds__(256, 2) void attn_tc(
    const float* __restrict__ qkv, float* __restrict__ attn_out)
{
    extern __shared__ unsigned sm[];
    unsigned* Qs = sm;              // [k8=8][ia=8][132]
    unsigned* Ks = Qs + 8448;       // [na=8][k8=8][70]
    unsigned* Vs = Ks + 4480;       // [na=8][k8=8][70]
    unsigned* Ps = Vs + 4480;       // [k8j=8][ia=8][132]
    float*    Osm = (float*)Ks;     // overlay: [64][132]

    const int i0 = blockIdx.x * 128, h = blockIdx.y, b = blockIdx.z;
    const float* qb = qkv + ((size_t)b * OQKV + h * DHEAD) * LSEQ;
    const float* kb = qb + (size_t)HID * LSEQ;
    const float* vb = kb + (size_t)HID * LSEQ;

    const int tid = threadIdx.x;
    const int warp = tid >> 5, lane = tid & 31;
    const int g = lane >> 2, t = lane & 3;
    const int phys = lane ^ g;

    // ---- stage Q (scaled by SCALE*log2e), tf32, A-frag layout ----
    const float QS = 0.125f * 1.44269504088896f;
    #pragma unroll
    for (int it = 0; it < 8; it++) {
        int d = warp + it * 8;
        int i4 = lane * 4;
        float4 q4 = *(const float4*)&qb[(size_t)d * LSEQ + i0 + i4];
        float qv[4] = {q4.x, q4.y, q4.z, q4.w};
        int k8 = d >> 3, tq = d & 3, kh = (d >> 2) & 1;
        #pragma unroll
        for (int e = 0; e < 4; e++) {
            int il = i4 + e;
            int ia = il >> 4, r = il & 15, gq = r & 7, mh = r >> 3;
            int ln = gq * 4 + tq, ph = ln ^ (ln >> 2);
            Qs[(k8 * 8 + ia) * 132 + ph * 4 + (mh + 2 * kh)] = f2tf(qv[e] * QS);
        }
    }

    float mrow[2] = {-1e30f, -1e30f};
    float lrow[2] = {0.0f, 0.0f};
    float o[8][4];
    #pragma unroll
    for (int i = 0; i < 8; i++)
        #pragma unroll
        for (int c = 0; c < 4; c++) o[i][c] = 0.0f;

    const int jt4 = (tid & 15) * 4;       // j offset for K/V loads
    const int drow0 = tid >> 4;           // base d row

    for (int j0 = 0; j0 < LSEQ; j0 += 64) {
        __syncthreads();   // previous consumers done (also covers Q staging)
        // ---- stage K, V tiles (64 d x 64 j), B-frag layout ----
        #pragma unroll
        for (int it = 0; it < 4; it++) {
            int d = drow0 + it * 16;
            float4 k4 = *(const float4*)&kb[(size_t)d * LSEQ + j0 + jt4];
            float4 v4 = *(const float4*)&vb[(size_t)d * LSEQ + j0 + jt4];
            float kv[4] = {k4.x, k4.y, k4.z, k4.w};
            float vv[4] = {v4.x, v4.y, v4.z, v4.w};
            // K: k-dim = d, n-dim = j
            int k8K = d >> 3, tK = d & 3, slK = (d >> 2) & 1;
            int naK = (tid & 15) >> 1;
            // V: k-dim = j, n-dim = d
            int naV = d >> 3, gV = d & 7;
            int k8V = (tid & 15) >> 1, slV = tid & 1;
            #pragma unroll
            for (int e = 0; e < 4; e++) {
                int gK = 4 * (tid & 1) + e;
                int lnK = gK * 4 + tK, phK = lnK ^ (lnK >> 2);
                Ks[(naK * 8 + k8K) * 70 + phK * 2 + slK] = f2tf(kv[e]);
                int lnV = gV * 4 + e, phV = lnV ^ (lnV >> 2);
                Vs[(naV * 8 + k8V) * 70 + phV * 2 + slV] = f2tf(vv[e]);
            }
        }
        __syncthreads();

        // ---- S = Q K (warp rows = warp*16 .. +15) ----
        float s[8][4];
        #pragma unroll
        for (int na = 0; na < 8; na++)
            #pragma unroll
            for (int c = 0; c < 4; c++) s[na][c] = 0.0f;
        #pragma unroll
        for (int k8 = 0; k8 < 8; k8++) {
            uint4 av = *(const uint4*)&Qs[(k8 * 8 + warp) * 132 + phys * 4];
            unsigned af[4] = {av.x, av.y, av.z, av.w};
            #pragma unroll
            for (int na = 0; na < 8; na++) {
                uint2 bf = *(const uint2*)&Ks[(na * 8 + k8) * 70 + phys * 2];
                unsigned bb[2] = {bf.x, bf.y};
                mma8(s[na], af, bb);
            }
        }

        // ---- online softmax (log2 domain), per row-half p ----
        #pragma unroll
        for (int p = 0; p < 2; p++) {
            float mx = -1e30f;
            #pragma unroll
            for (int na = 0; na < 8; na++)
                mx = fmaxf(mx, fmaxf(s[na][2 * p], s[na][2 * p + 1]));
            mx = fmaxf(mx, __shfl_xor_sync(0xffffffffu, mx, 1));
            mx = fmaxf(mx, __shfl_xor_sync(0xffffffffu, mx, 2));
            float mnew = fmaxf(mrow[p], mx);
            float resc = fast_ex2(mrow[p] - mnew);
            mrow[p] = mnew;
            float sum = 0.0f;
            #pragma unroll
            for (int na = 0; na < 8; na++) {
                float v0 = fast_ex2(s[na][2 * p] - mnew);
                float v1 = fast_ex2(s[na][2 * p + 1] - mnew);
                s[na][2 * p] = v0; s[na][2 * p + 1] = v1;
                sum += v0 + v1;
            }
            sum += __shfl_xor_sync(0xffffffffu, sum, 1);
            sum += __shfl_xor_sync(0xffffffffu, sum, 2);
            lrow[p] = lrow[p] * resc + sum;
            #pragma unroll
            for (int na = 0; na < 8; na++) {
                o[na][2 * p]     *= resc;
                o[na][2 * p + 1] *= resc;
            }
        }

        // ---- P -> warp-private smem in A-frag layout ----
        #pragma unroll
        for (int na = 0; na < 8; na++) {
            #pragma unroll
            for (int p = 0; p < 2; p++) {
                #pragma unroll
                for (int e = 0; e < 2; e++) {
                    int jc = 2 * t + e;               // col within atom (0..7)
                    int tP = jc & 3, khP = jc >> 2;
                    int ln = g * 4 + tP, ph = ln ^ (ln >> 2);
                    Ps[(na * 8 + warp) * 132 + ph * 4 + (p + 2 * khP)] =
                        f2tf(s[na][2 * p + e]);
                }
            }
        }
        __syncwarp();

        // ---- O += P V ----
        #pragma unroll
        for (int k8 = 0; k8 < 8; k8++) {
            uint4 av = *(const uint4*)&Ps[(k8 * 8 + warp) * 132 + phys * 4];
            unsigned af[4] = {av.x, av.y, av.z, av.w};
            #pragma unroll
            for (int na = 0; na < 8; na++) {
                uint2 bf = *(const uint2*)&Vs[(na * 8 + k8) * 70 + phys * 2];
                unsigned bb[2] = {bf.x, bf.y};
                mma8(o[na], af, bb);
            }
        }
    }

    // ---- epilogue: normalize, transpose via smem, coalesced write ----
    float inv0 = 1.0f / lrow[0], inv1 = 1.0f / lrow[1];
    __syncthreads();
    #pragma unroll
    for (int na = 0; na < 8; na++) {
        int d0 = na * 8 + 2 * t;
        int irow = warp * 16 + g;
        Osm[(size_t)d0 * 132 + irow]           = o[na][0] * inv0;
        Osm[(size_t)(d0 + 1) * 132 + irow]     = o[na][1] * inv0;
        Osm[(size_t)d0 * 132 + irow + 8]       = o[na][2] * inv1;
        Osm[(size_t)(d0 + 1) * 132 + irow + 8] = o[na][3] * inv1;
    }
    __syncthreads();
    float* ob = attn_out + ((size_t)b * HID + h * DHEAD) * LSEQ;
    #pragma unroll
    for (int it = 0; it < 8; it++) {
        int lin = it * 1024 + tid * 4;
        int d = lin >> 7, i = lin & 127;
        float4 v = *(const float4*)&Osm[(size_t)d * 132 + i];
        *(float4*)&ob[(size_t)d * LSEQ + i0 + i] = v;
    }
}

// ---------------------------------------------------------------------------
extern "C" void kernel_launch(void* const* d_in, const int* in_sizes, int n_in,
                              void* d_out, int out_size)
{
    const float* x     = (const float*)d_in[0];
    const float* w_qkv = (const float*)d_in[1];
    const float* w_out = (const float*)d_in[2];
    const float* b_out = (const float*)d_in[3];
    float*       out   = (float*)d_out;

    float *qkv_ptr, *attn_ptr;
    cudaGetSymbolAddress((void**)&qkv_ptr, g_qkv);
    cudaGetSymbolAddress((void**)&attn_ptr, g_attn);

    // 1) QKV projection
    {
        dim3 grid(LSEQ / 128, OQKV / 128, BATCH);
        gemm_tc<<<grid, 256>>>(w_qkv, x, qkv_ptr, OQKV, LSEQ, CDIM, nullptr);
    }
    // 2) attention
    {
        int smem = ATT_SMEM_WORDS * (int)sizeof(unsigned);
        cudaFuncSetAttribute(attn_tc,
                             cudaFuncAttributeMaxDynamicSharedMemorySize, smem);
        dim3 grid(LSEQ / 128, NHEADS, BATCH);
        attn_tc<<<grid, 256, smem>>>(qkv_ptr, attn_ptr);
    }
    // 3) out projection + bias
    {
        dim3 grid(LSEQ / 128, HID / 128, BATCH);
        gemm_tc<<<grid, 256>>>(w_out, attn_ptr, out, HID, LSEQ, HID, b_out);
    }
}